// round 9
// baseline (speedup 1.0000x reference)
#include <cuda_runtime.h>
#include <math.h>

#define B_   64
#define T_   200
#define TP1_ 201
#define D_   128
#define M_   64
#define NQ_  13523
#define BT_  (B_*T_)          // 12800

// ---------------- scratch (no allocation allowed) ----------------
__device__ float g_k  [BT_*D_];
__device__ float g_w  [BT_*M_];
__device__ float g_e  [BT_*D_];
__device__ float g_a  [BT_*D_];
__device__ float g_rp0[BT_*D_];
__device__ float g_rp1[BT_*D_];
__device__ float g_rp2[BT_*D_];
__device__ float g_rp3[BT_*D_];

__device__ __forceinline__ float sigmoidf_(float x) { return 1.0f/(1.0f+expf(-x)); }

// ---- packed fp32x2 helpers (sm_103a FFMA2 path, PTX-only) ----
__device__ __forceinline__ unsigned long long pack2(float x, float y) {
    unsigned long long r;
    asm("mov.b64 %0, {%1, %2};" : "=l"(r) : "f"(x), "f"(y));
    return r;
}
__device__ __forceinline__ void ffma2(unsigned long long& d, unsigned long long a, unsigned long long b) {
    asm("fma.rn.f32x2 %0, %1, %2, %0;" : "+l"(d) : "l"(a), "l"(b));
}
__device__ __forceinline__ void unpack2(unsigned long long v, float& x, float& y) {
    asm("mov.b64 {%0, %1}, %2;" : "=f"(x), "=f"(y) : "l"(v));
}

// 4 rows x 8 cols step (wsoft)
__device__ __forceinline__ void mm_step4(unsigned long long acc[4][4],
                                         const float* sxT, const float* swT,
                                         int k, int ti, int tn) {
    float4 xv = *(const float4*)(sxT + k*68 + ti*4);
    ulonglong2 b0 = *(const ulonglong2*)(swT + k*68 + tn*8);
    ulonglong2 b1 = *(const ulonglong2*)(swT + k*68 + tn*8 + 4);
    unsigned long long a;
    a = pack2(xv.x, xv.x);
    ffma2(acc[0][0],a,b0.x); ffma2(acc[0][1],a,b0.y); ffma2(acc[0][2],a,b1.x); ffma2(acc[0][3],a,b1.y);
    a = pack2(xv.y, xv.y);
    ffma2(acc[1][0],a,b0.x); ffma2(acc[1][1],a,b0.y); ffma2(acc[1][2],a,b1.x); ffma2(acc[1][3],a,b1.y);
    a = pack2(xv.z, xv.z);
    ffma2(acc[2][0],a,b0.x); ffma2(acc[2][1],a,b0.y); ffma2(acc[2][2],a,b1.x); ffma2(acc[2][3],a,b1.y);
    a = pack2(xv.w, xv.w);
    ffma2(acc[3][0],a,b0.x); ffma2(acc[3][1],a,b0.y); ffma2(acc[3][2],a,b1.x); ffma2(acc[3][3],a,b1.y);
}

// 4 rows x 16 cols step: A 1xLDS.128 (2wf/warp dedup), B 4xLDS.128 broadcast.
// wstride = row stride of swT in floats.
template<int WSTRIDE>
__device__ __forceinline__ void mm_step16(unsigned long long acc[4][8],
                                          const float* sxT, const float* swT,
                                          int k, int ti, int tn) {
    float4 xv = *(const float4*)(sxT + k*68 + ti*4);
    const float* bp = swT + k*WSTRIDE + tn*16;
    ulonglong2 b0 = *(const ulonglong2*)(bp);
    ulonglong2 b1 = *(const ulonglong2*)(bp + 4);
    ulonglong2 b2 = *(const ulonglong2*)(bp + 8);
    ulonglong2 b3 = *(const ulonglong2*)(bp + 12);
    unsigned long long a;
    a = pack2(xv.x, xv.x);
    ffma2(acc[0][0],a,b0.x); ffma2(acc[0][1],a,b0.y); ffma2(acc[0][2],a,b1.x); ffma2(acc[0][3],a,b1.y);
    ffma2(acc[0][4],a,b2.x); ffma2(acc[0][5],a,b2.y); ffma2(acc[0][6],a,b3.x); ffma2(acc[0][7],a,b3.y);
    a = pack2(xv.y, xv.y);
    ffma2(acc[1][0],a,b0.x); ffma2(acc[1][1],a,b0.y); ffma2(acc[1][2],a,b1.x); ffma2(acc[1][3],a,b1.y);
    ffma2(acc[1][4],a,b2.x); ffma2(acc[1][5],a,b2.y); ffma2(acc[1][6],a,b3.x); ffma2(acc[1][7],a,b3.y);
    a = pack2(xv.z, xv.z);
    ffma2(acc[2][0],a,b0.x); ffma2(acc[2][1],a,b0.y); ffma2(acc[2][2],a,b1.x); ffma2(acc[2][3],a,b1.y);
    ffma2(acc[2][4],a,b2.x); ffma2(acc[2][5],a,b2.y); ffma2(acc[2][6],a,b3.x); ffma2(acc[2][7],a,b3.y);
    a = pack2(xv.w, xv.w);
    ffma2(acc[3][0],a,b0.x); ffma2(acc[3][1],a,b0.y); ffma2(acc[3][2],a,b1.x); ffma2(acc[3][3],a,b1.y);
    ffma2(acc[3][4],a,b2.x); ffma2(acc[3][5],a,b2.y); ffma2(acc[3][6],a,b3.x); ffma2(acc[3][7],a,b3.y);
}

// =================================================================
// Kernel 1: wsoft (k gather + softmax(k @ Mk^T)). 64x64, 4x8 tiles. (R5 proven)
// =================================================================
__global__ void __launch_bounds__(128) k_wsoft(const int* __restrict__ q,
                                               const float* __restrict__ k_emb,
                                               const float* __restrict__ Mk) {
    __shared__ __align__(16) float sxT[32*68];
    __shared__ __align__(16) float swT[32*68];
    __shared__ float sc[64*65];
    __shared__ int sq[64];
    const int tid  = threadIdx.x;
    const int row0 = blockIdx.x * 64;
    const int ti = tid & 15, tn = tid >> 4;
    int rA[4], kA[4];
#pragma unroll
    for (int it = 0; it < 4; it++) {
        int idx = it*128 + tid;
        rA[it] = idx >> 3; kA[it] = (idx & 7) << 2;
    }
    if (tid < 64) sq[tid] = q[row0 + tid];
    __syncthreads();

    float4 xr[4], wr[4];
#pragma unroll
    for (int it = 0; it < 4; it++) {
        xr[it] = *(const float4*)(k_emb + (size_t)sq[rA[it]]*D_ + kA[it]);
        wr[it] = *(const float4*)(Mk    + (size_t)rA[it]*D_ + kA[it]);
    }
    unsigned long long acc[4][4] = {};
    for (int kc = 0; kc < 4; kc++) {
        if (kc) __syncthreads();
#pragma unroll
        for (int it = 0; it < 4; it++) {
            int k4 = kA[it], row = rA[it];
            sxT[(k4+0)*68+row]=xr[it].x; sxT[(k4+1)*68+row]=xr[it].y;
            sxT[(k4+2)*68+row]=xr[it].z; sxT[(k4+3)*68+row]=xr[it].w;
            swT[(k4+0)*68+row]=wr[it].x; swT[(k4+1)*68+row]=wr[it].y;
            swT[(k4+2)*68+row]=wr[it].z; swT[(k4+3)*68+row]=wr[it].w;
            *(float4*)(g_k + (size_t)(row0+row)*D_ + kc*32 + k4) = xr[it];
        }
        __syncthreads();
        if (kc < 3) {
            int kk = (kc+1)*32;
#pragma unroll
            for (int it = 0; it < 4; it++) {
                xr[it] = *(const float4*)(k_emb + (size_t)sq[rA[it]]*D_ + kk + kA[it]);
                wr[it] = *(const float4*)(Mk    + (size_t)rA[it]*D_ + kk + kA[it]);
            }
        }
#pragma unroll 8
        for (int k = 0; k < 32; k++) mm_step4(acc, sxT, swT, k, ti, tn);
    }
#pragma unroll
    for (int i = 0; i < 4; i++)
#pragma unroll
        for (int c = 0; c < 4; c++) {
            float lo, hi; unpack2(acc[i][c], lo, hi);
            sc[(ti*4+i)*65 + tn*8 + 2*c]     = lo;
            sc[(ti*4+i)*65 + tn*8 + 2*c + 1] = hi;
        }
    __syncthreads();
    if (tid < 64) {
        float mx = -1e30f;
#pragma unroll
        for (int m = 0; m < M_; m++) mx = fmaxf(mx, sc[tid*65 + m]);
        float s = 0.f;
#pragma unroll
        for (int m = 0; m < M_; m++) { float e = expf(sc[tid*65+m]-mx); sc[tid*65+m]=e; s+=e; }
        float inv = 1.0f / s;
#pragma unroll
        for (int m = 0; m < M_; m++)
            g_w[(size_t)(row0+tid)*M_ + m] = sc[tid*65+m]*inv;
    }
}

// =================================================================
// Kernel 2: fused e+a GEMM. 256 threads, 64 rows x 256 cols (e|a), 4x16 tiles.
// v gathered once. cols 0..127 -> e (sigmoid), 128..255 -> a (tanh).
// =================================================================
__global__ void __launch_bounds__(256) k_ea(const int* __restrict__ q, const int* __restrict__ rr,
                                            const float* __restrict__ v_emb,
                                            const float* __restrict__ eW, const float* __restrict__ ebv,
                                            const float* __restrict__ aW, const float* __restrict__ abv) {
    __shared__ __align__(16) float sxT[32*68];
    __shared__ __align__(16) float swT[32*264];
    __shared__ int sq[64];
    const int tid  = threadIdx.x;
    const int row0 = blockIdx.x * 64;
    const int ti = tid & 15, tn = tid >> 4;   // rows ti*4.., cols tn*16..

    int rA[2], kA[2], nB[8], kB[8];
#pragma unroll
    for (int it = 0; it < 2; it++) {
        int idx = it*256 + tid;
        rA[it] = idx >> 3; kA[it] = (idx & 7) << 2;
    }
#pragma unroll
    for (int it = 0; it < 8; it++) {
        int idx = it*256 + tid;
        nB[it] = idx >> 3; kB[it] = (idx & 7) << 2;   // nB 0..255
    }
    if (tid < 64) { int row = row0 + tid; sq[tid] = q[row] + NQ_ * rr[row]; }
    __syncthreads();

    auto loadW = [&](int n, int kk) -> float4 {
        const float* Wp = (n < 128) ? (eW + (size_t)n*D_) : (aW + (size_t)(n-128)*D_);
        return *(const float4*)(Wp + kk);
    };

    float4 xr[2], wr[8];
#pragma unroll
    for (int it = 0; it < 2; it++)
        xr[it] = *(const float4*)(v_emb + (size_t)sq[rA[it]]*D_ + kA[it]);
#pragma unroll
    for (int it = 0; it < 8; it++)
        wr[it] = loadW(nB[it], kB[it]);

    unsigned long long acc[4][8] = {};
    for (int kc = 0; kc < 4; kc++) {
        if (kc) __syncthreads();
#pragma unroll
        for (int it = 0; it < 2; it++) {
            int k4 = kA[it], row = rA[it];
            sxT[(k4+0)*68+row]=xr[it].x; sxT[(k4+1)*68+row]=xr[it].y;
            sxT[(k4+2)*68+row]=xr[it].z; sxT[(k4+3)*68+row]=xr[it].w;
        }
#pragma unroll
        for (int it = 0; it < 8; it++) {
            int k4 = kB[it], n = nB[it];
            swT[(k4+0)*264+n]=wr[it].x; swT[(k4+1)*264+n]=wr[it].y;
            swT[(k4+2)*264+n]=wr[it].z; swT[(k4+3)*264+n]=wr[it].w;
        }
        __syncthreads();
        if (kc < 3) {
            int kk = (kc+1)*32;
#pragma unroll
            for (int it = 0; it < 2; it++)
                xr[it] = *(const float4*)(v_emb + (size_t)sq[rA[it]]*D_ + kk + kA[it]);
#pragma unroll
            for (int it = 0; it < 8; it++)
                wr[it] = loadW(nB[it], kk + kB[it]);
        }
#pragma unroll 4
        for (int k = 0; k < 32; k++) mm_step16<264>(acc, sxT, swT, k, ti, tn);
    }

    const bool is_e = (tn < 8);
    const int n0 = (tn & 7) * 16;                 // col within the 128-wide output
    const float* bias = is_e ? ebv : abv;
    float* gout = is_e ? g_e : g_a;
    float b[16];
#pragma unroll
    for (int j = 0; j < 16; j++) b[j] = bias[n0+j];
#pragma unroll
    for (int i = 0; i < 4; i++) {
        float y[16];
#pragma unroll
        for (int c = 0; c < 8; c++) { unpack2(acc[i][c], y[2*c], y[2*c+1]); }
        size_t row = (size_t)(row0 + ti*4 + i);
        float o[16];
        if (is_e) {
#pragma unroll
            for (int j = 0; j < 16; j++) o[j] = sigmoidf_(y[j]+b[j]);
        } else {
#pragma unroll
            for (int j = 0; j < 16; j++) o[j] = tanhf(y[j]+b[j]);
        }
#pragma unroll
        for (int j = 0; j < 16; j += 4)
            *(float4*)(gout + row*D_ + n0 + j) = make_float4(o[j],o[j+1],o[j+2],o[j+3]);
    }
}

// =================================================================
// Kernel 3: sequential scan. grid (B, 4 m-chunks of 16), 128 thr (one d each).
// NO block syncs: w broadcast via direct LDG (L1 broadcast), prefetched 1 step.
// =================================================================
__global__ void __launch_bounds__(128) k_scan(const float* __restrict__ Mv0, float* __restrict__ out) {
    const int b   = blockIdx.x;
    const int mc  = blockIdx.y;
    const int tid = threadIdx.x;   // d
    const int m0  = mc * 16;
    float Mv[16];

    float* mvout = out + BT_ + (size_t)b * TP1_ * M_ * D_;
#pragma unroll
    for (int i = 0; i < 16; i++) {
        float v = Mv0[(m0 + i) * D_ + tid];
        Mv[i] = v;
        __stcs(mvout + (size_t)(m0 + i) * D_ + tid, v);   // t = 0 slice
    }

    const float* wb  = g_w + (size_t)b * T_ * M_ + m0;
    const float* ebp = g_e + (size_t)b * T_ * D_ + tid;
    const float* abp = g_a + (size_t)b * T_ * D_ + tid;
    float* rp = ((mc==0)?g_rp0:(mc==1)?g_rp1:(mc==2)?g_rp2:g_rp3) + (size_t)b * T_ * D_ + tid;

    float4 w0 = *(const float4*)(wb);
    float4 w1 = *(const float4*)(wb + 4);
    float4 w2 = *(const float4*)(wb + 8);
    float4 w3 = *(const float4*)(wb + 12);
    float ecur = ebp[0], acur = abp[0];
    float* orow = mvout + (size_t)M_ * D_ + (size_t)m0 * D_ + tid;

    for (int t = 0; t < T_; t++) {
        float4 nw0=w0, nw1=w1, nw2=w2, nw3=w3;
        float enx = ecur, anx = acur;
        if (t + 1 < T_) {
            const float* wn = wb + (size_t)(t+1)*M_;
            nw0 = *(const float4*)(wn);     nw1 = *(const float4*)(wn + 4);
            nw2 = *(const float4*)(wn + 8); nw3 = *(const float4*)(wn + 12);
            enx = ebp[(size_t)(t+1)*D_];
            anx = abp[(size_t)(t+1)*D_];
        }
        float wv[16] = {w0.x,w0.y,w0.z,w0.w, w1.x,w1.y,w1.z,w1.w,
                        w2.x,w2.y,w2.z,w2.w, w3.x,w3.y,w3.z,w3.w};
        float r0=0.f, r1=0.f;
#pragma unroll
        for (int i = 0; i < 16; i++) {
            float wvi = wv[i];
            if (i & 1) r1 = fmaf(wvi, Mv[i], r1); else r0 = fmaf(wvi, Mv[i], r0);
            Mv[i] = fmaf(wvi, acur, Mv[i] * fmaf(-wvi, ecur, 1.0f));    // Mv*(1-w e)+w a
            __stcs(orow + (size_t)i * D_, Mv[i]);
        }
        rp[(size_t)t * D_] = r0 + r1;
        w0=nw0; w1=nw1; w2=nw2; w3=nw3;
        ecur = enx; acur = anx;
        orow += (size_t)M_ * D_;
    }
}

// =================================================================
// Kernel 4: read = sum(rp0..3); f = tanh([read,k]@fW^T + fb);
// p = sigmoid(f . pW + pb). 64 rows x 128 cols, 128 threads, 4x16 tiles.
// =================================================================
__global__ void __launch_bounds__(128) k_fp(const float* __restrict__ fW, const float* __restrict__ fb,
                                            const float* __restrict__ pW, const float* __restrict__ pb,
                                            float* __restrict__ out) {
    __shared__ __align__(16) float sxT[32*68];
    __shared__ __align__(16) float swT[32*132];
    __shared__ float sp[64*9];
    const int tid  = threadIdx.x;
    const int row0 = blockIdx.x * 64;
    const int ti = tid & 15, tn = tid >> 4;   // rows ti*4.., cols tn*16..

    int rA[4], kA[4], nB[8], kB[8];
#pragma unroll
    for (int it = 0; it < 4; it++) {
        int idx = it*128 + tid;
        rA[it] = idx >> 3; kA[it] = (idx & 7) << 2;
    }
#pragma unroll
    for (int it = 0; it < 8; it++) {
        int idx = it*128 + tid;
        nB[it] = idx >> 3; kB[it] = (idx & 7) << 2;
    }

    auto loadX = [&](int row, int kk) -> float4 {
        if (kk < 128) {
            size_t g = (size_t)(row0+row)*D_ + kk;
            float4 a0 = *(const float4*)(g_rp0+g);
            float4 a1 = *(const float4*)(g_rp1+g);
            float4 a2 = *(const float4*)(g_rp2+g);
            float4 a3 = *(const float4*)(g_rp3+g);
            float4 v;
            v.x=(a0.x+a1.x)+(a2.x+a3.x); v.y=(a0.y+a1.y)+(a2.y+a3.y);
            v.z=(a0.z+a1.z)+(a2.z+a3.z); v.w=(a0.w+a1.w)+(a2.w+a3.w);
            return v;
        }
        return *(const float4*)(g_k + (size_t)(row0+row)*D_ + (kk-128));
    };

    float4 xr[4], wr[8];
#pragma unroll
    for (int it = 0; it < 4; it++) xr[it] = loadX(rA[it], kA[it]);
#pragma unroll
    for (int it = 0; it < 8; it++) wr[it] = *(const float4*)(fW + (size_t)nB[it]*256 + kB[it]);

    unsigned long long acc[4][8] = {};
    for (int kc = 0; kc < 8; kc++) {
        if (kc) __syncthreads();
#pragma unroll
        for (int it = 0; it < 4; it++) {
            int k4 = kA[it], row = rA[it];
            sxT[(k4+0)*68+row]=xr[it].x; sxT[(k4+1)*68+row]=xr[it].y;
            sxT[(k4+2)*68+row]=xr[it].z; sxT[(k4+3)*68+row]=xr[it].w;
        }
#pragma unroll
        for (int it = 0; it < 8; it++) {
            int k4 = kB[it], n = nB[it];
            swT[(k4+0)*132+n]=wr[it].x; swT[(k4+1)*132+n]=wr[it].y;
            swT[(k4+2)*132+n]=wr[it].z; swT[(k4+3)*132+n]=wr[it].w;
        }
        __syncthreads();
        if (kc < 7) {
            int kk = (kc+1)*32;
#pragma unroll
            for (int it = 0; it < 4; it++) xr[it] = loadX(rA[it], kk + kA[it]);
#pragma unroll
            for (int it = 0; it < 8; it++) wr[it] = *(const float4*)(fW + (size_t)nB[it]*256 + kk + kB[it]);
        }
#pragma unroll 4
        for (int k = 0; k < 32; k++) mm_step16<132>(acc, sxT, swT, k, ti, tn);
    }

    // epilogue: f = tanh(acc + fb), partial p = sum pW*f over this thread's 16 cols
    float ps[4] = {};
    const int n0 = tn * 16;
#pragma unroll
    for (int c = 0; c < 8; c++) {
        int n = n0 + 2*c;
        float blo = fb[n], bhi = fb[n+1];
        float wlo = pW[n], whi = pW[n+1];
#pragma unroll
        for (int i = 0; i < 4; i++) {
            float lo, hi; unpack2(acc[i][c], lo, hi);
            ps[i] = fmaf(wlo, tanhf(lo + blo), ps[i]);
            ps[i] = fmaf(whi, tanhf(hi + bhi), ps[i]);
        }
    }
#pragma unroll
    for (int i = 0; i < 4; i++) sp[(ti*4+i)*9 + tn] = ps[i];
    __syncthreads();
    if (tid < 64) {
        float s = pb[0];
#pragma unroll
        for (int g2 = 0; g2 < 8; g2++) s += sp[tid*9 + g2];
        out[row0 + tid] = 1.0f / (1.0f + expf(-s));
    }
}

// =================================================================
extern "C" void kernel_launch(void* const* d_in, const int* in_sizes, int n_in,
                              void* d_out, int out_size) {
    const int*   q     = (const int*)  d_in[0];
    const int*   r     = (const int*)  d_in[1];
    const float* k_emb = (const float*)d_in[2];
    const float* v_emb = (const float*)d_in[3];
    const float* Mk    = (const float*)d_in[4];
    const float* Mv0   = (const float*)d_in[5];
    const float* fW    = (const float*)d_in[6];
    const float* fb    = (const float*)d_in[7];
    const float* pW    = (const float*)d_in[8];
    const float* pb    = (const float*)d_in[9];
    const float* eW    = (const float*)d_in[10];
    const float* eb    = (const float*)d_in[11];
    const float* aW    = (const float*)d_in[12];
    const float* ab    = (const float*)d_in[13];
    float* out = (float*)d_out;

    k_wsoft<<<BT_/64, 128>>>(q, k_emb, Mk);
    k_ea   <<<BT_/64, 256>>>(q, r, v_emb, eW, eb, aW, ab);
    k_scan <<<dim3(B_, 4), 128>>>(Mv0, out);
    k_fp   <<<BT_/64, 128>>>(fW, fb, pW, pb, out);
}

// round 10
// speedup vs baseline: 1.2467x; 1.2467x over previous
#include <cuda_runtime.h>
#include <math.h>

#define B_   64
#define T_   200
#define TP1_ 201
#define D_   128
#define M_   64
#define NQ_  13523
#define BT_  (B_*T_)          // 12800

// ---------------- scratch (no allocation allowed) ----------------
__device__ float g_k  [BT_*D_];
__device__ float g_w  [BT_*M_];
__device__ float g_e  [BT_*D_];
__device__ float g_a  [BT_*D_];
__device__ float g_rp0[BT_*D_];
__device__ float g_rp1[BT_*D_];
__device__ float g_rp2[BT_*D_];
__device__ float g_rp3[BT_*D_];

__device__ __forceinline__ float sigmoidf_(float x) { return 1.0f/(1.0f+expf(-x)); }

// ---- packed fp32x2 helpers (sm_103a FFMA2 path, PTX-only) ----
__device__ __forceinline__ unsigned long long pack2(float x, float y) {
    unsigned long long r;
    asm("mov.b64 %0, {%1, %2};" : "=l"(r) : "f"(x), "f"(y));
    return r;
}
__device__ __forceinline__ void ffma2(unsigned long long& d, unsigned long long a, unsigned long long b) {
    asm("fma.rn.f32x2 %0, %1, %2, %0;" : "+l"(d) : "l"(a), "l"(b));
}
__device__ __forceinline__ void unpack2(unsigned long long v, float& x, float& y) {
    asm("mov.b64 {%0, %1}, %2;" : "=f"(x), "=f"(y) : "l"(v));
}

// shared inner product step: 4 rows x 8 cols, one k
template<int XS, int WS>
__device__ __forceinline__ void mm_step(unsigned long long acc[4][4],
                                        const float* sxT, const float* swT,
                                        int k, int ti, int tn) {
    float4 xv = *(const float4*)(sxT + k*XS + ti*4);
    ulonglong2 b0 = *(const ulonglong2*)(swT + k*WS + tn*8);
    ulonglong2 b1 = *(const ulonglong2*)(swT + k*WS + tn*8 + 4);
    unsigned long long a;
    a = pack2(xv.x, xv.x);
    ffma2(acc[0][0],a,b0.x); ffma2(acc[0][1],a,b0.y); ffma2(acc[0][2],a,b1.x); ffma2(acc[0][3],a,b1.y);
    a = pack2(xv.y, xv.y);
    ffma2(acc[1][0],a,b0.x); ffma2(acc[1][1],a,b0.y); ffma2(acc[1][2],a,b1.x); ffma2(acc[1][3],a,b1.y);
    a = pack2(xv.z, xv.z);
    ffma2(acc[2][0],a,b0.x); ffma2(acc[2][1],a,b0.y); ffma2(acc[2][2],a,b1.x); ffma2(acc[2][3],a,b1.y);
    a = pack2(xv.w, xv.w);
    ffma2(acc[3][0],a,b0.x); ffma2(acc[3][1],a,b0.y); ffma2(acc[3][2],a,b1.x); ffma2(acc[3][3],a,b1.y);
}

// =================================================================
// Merged kernel: grid (200, 5). y==0 -> wsoft (k gather + softmax(k@Mk^T))
//                               y in 1..4 -> e/a GEMMs.
// Software-pipelined: prefetch next K-chunk into regs during compute.
// =================================================================
#define SM_SXT 0
#define SM_SWT (32*68)
#define SM_AUX (2*32*68)          // ea: sq ; wsoft: sc[64*65] then sq
#define SM_TOTAL (SM_AUX + 64*65 + 64)

__global__ void __launch_bounds__(128) k_we(const int* __restrict__ q, const int* __restrict__ rr,
                                            const float* __restrict__ k_emb, const float* __restrict__ Mk,
                                            const float* __restrict__ v_emb,
                                            const float* __restrict__ eW, const float* __restrict__ ebv,
                                            const float* __restrict__ aW, const float* __restrict__ abv) {
    __shared__ __align__(16) float smbuf[SM_TOTAL];
    float* sxT = smbuf + SM_SXT;
    float* swT = smbuf + SM_SWT;
    const int tid  = threadIdx.x;
    const int row0 = blockIdx.x * 64;
    const int yb   = blockIdx.y;
    const int ti = tid & 15, tn = tid >> 4;

    int rA[4], kA[4];
#pragma unroll
    for (int it = 0; it < 4; it++) {
        int idx = it*128 + tid;
        rA[it] = idx >> 3;
        kA[it] = (idx & 7) << 2;
    }

    if (yb == 0) {
        // ---------------- wsoft ----------------
        float* sc = smbuf + SM_AUX;
        int*   sq = (int*)(smbuf + SM_AUX + 64*65);
        if (tid < 64) sq[tid] = q[row0 + tid];
        __syncthreads();

        float4 xr[4], wr[4];
#pragma unroll
        for (int it = 0; it < 4; it++) {
            xr[it] = *(const float4*)(k_emb + (size_t)sq[rA[it]]*D_ + kA[it]);
            wr[it] = *(const float4*)(Mk    + (size_t)rA[it]*D_ + kA[it]);
        }
        unsigned long long acc[4][4] = {};
        for (int kc = 0; kc < 4; kc++) {
            if (kc) __syncthreads();
#pragma unroll
            for (int it = 0; it < 4; it++) {
                int k4 = kA[it], row = rA[it];
                sxT[(k4+0)*68+row]=xr[it].x; sxT[(k4+1)*68+row]=xr[it].y;
                sxT[(k4+2)*68+row]=xr[it].z; sxT[(k4+3)*68+row]=xr[it].w;
                swT[(k4+0)*68+row]=wr[it].x; swT[(k4+1)*68+row]=wr[it].y;
                swT[(k4+2)*68+row]=wr[it].z; swT[(k4+3)*68+row]=wr[it].w;
                *(float4*)(g_k + (size_t)(row0+row)*D_ + kc*32 + k4) = xr[it];
            }
            __syncthreads();
            if (kc < 3) {
                int kk = (kc+1)*32;
#pragma unroll
                for (int it = 0; it < 4; it++) {
                    xr[it] = *(const float4*)(k_emb + (size_t)sq[rA[it]]*D_ + kk + kA[it]);
                    wr[it] = *(const float4*)(Mk    + (size_t)rA[it]*D_ + kk + kA[it]);
                }
            }
#pragma unroll 8
            for (int k = 0; k < 32; k++) mm_step<68,68>(acc, sxT, swT, k, ti, tn);
        }
#pragma unroll
        for (int i = 0; i < 4; i++)
#pragma unroll
            for (int c = 0; c < 4; c++) {
                float lo, hi; unpack2(acc[i][c], lo, hi);
                sc[(ti*4+i)*65 + tn*8 + 2*c]     = lo;
                sc[(ti*4+i)*65 + tn*8 + 2*c + 1] = hi;
            }
        __syncthreads();
        if (tid < 64) {
            float mx = -1e30f;
#pragma unroll
            for (int m = 0; m < M_; m++) mx = fmaxf(mx, sc[tid*65 + m]);
            float s = 0.f;
#pragma unroll
            for (int m = 0; m < M_; m++) { float e = expf(sc[tid*65+m]-mx); sc[tid*65+m]=e; s+=e; }
            float inv = 1.0f / s;
#pragma unroll
            for (int m = 0; m < M_; m++)
                g_w[(size_t)(row0+tid)*M_ + m] = sc[tid*65+m]*inv;
        }
    } else {
        // ---------------- e/a GEMM ----------------
        const int nc = yb - 1;
        int* sq = (int*)(smbuf + SM_AUX);
        const float* W    = (nc < 2) ? eW  : aW;
        const float* bias = (nc < 2) ? ebv : abv;
        const int coloff  = (nc & 1) * 64;
        if (tid < 64) { int row = row0 + tid; sq[tid] = q[row] + NQ_ * rr[row]; }
        __syncthreads();

        float4 xr[4], wr[4];
#pragma unroll
        for (int it = 0; it < 4; it++) {
            xr[it] = *(const float4*)(v_emb + (size_t)sq[rA[it]]*D_ + kA[it]);
            wr[it] = *(const float4*)(W + (size_t)(coloff + rA[it])*D_ + kA[it]);
        }
        unsigned long long acc[4][4] = {};
        for (int kc = 0; kc < 4; kc++) {
            if (kc) __syncthreads();
#pragma unroll
            for (int it = 0; it < 4; it++) {
                int k4 = kA[it], row = rA[it];
                sxT[(k4+0)*68+row]=xr[it].x; sxT[(k4+1)*68+row]=xr[it].y;
                sxT[(k4+2)*68+row]=xr[it].z; sxT[(k4+3)*68+row]=xr[it].w;
                swT[(k4+0)*68+row]=wr[it].x; swT[(k4+1)*68+row]=wr[it].y;
                swT[(k4+2)*68+row]=wr[it].z; swT[(k4+3)*68+row]=wr[it].w;
            }
            __syncthreads();
            if (kc < 3) {
                int kk = (kc+1)*32;
#pragma unroll
                for (int it = 0; it < 4; it++) {
                    xr[it] = *(const float4*)(v_emb + (size_t)sq[rA[it]]*D_ + kk + kA[it]);
                    wr[it] = *(const float4*)(W + (size_t)(coloff + rA[it])*D_ + kk + kA[it]);
                }
            }
#pragma unroll 8
            for (int k = 0; k < 32; k++) mm_step<68,68>(acc, sxT, swT, k, ti, tn);
        }
        const int n0 = coloff + tn*8;
        float b[8];
#pragma unroll
        for (int j = 0; j < 8; j++) b[j] = bias[n0+j];
#pragma unroll
        for (int i = 0; i < 4; i++) {
            float y[8];
#pragma unroll
            for (int c = 0; c < 4; c++) { unpack2(acc[i][c], y[2*c], y[2*c+1]); }
            size_t row = (size_t)(row0 + ti*4 + i);
            float4 o0, o1;
            if (nc < 2) {
                o0.x=sigmoidf_(y[0]+b[0]); o0.y=sigmoidf_(y[1]+b[1]); o0.z=sigmoidf_(y[2]+b[2]); o0.w=sigmoidf_(y[3]+b[3]);
                o1.x=sigmoidf_(y[4]+b[4]); o1.y=sigmoidf_(y[5]+b[5]); o1.z=sigmoidf_(y[6]+b[6]); o1.w=sigmoidf_(y[7]+b[7]);
                *(float4*)(g_e + row*D_ + n0)     = o0;
                *(float4*)(g_e + row*D_ + n0 + 4) = o1;
            } else {
                o0.x=tanhf(y[0]+b[0]); o0.y=tanhf(y[1]+b[1]); o0.z=tanhf(y[2]+b[2]); o0.w=tanhf(y[3]+b[3]);
                o1.x=tanhf(y[4]+b[4]); o1.y=tanhf(y[5]+b[5]); o1.z=tanhf(y[6]+b[6]); o1.w=tanhf(y[7]+b[7]);
                *(float4*)(g_a + row*D_ + n0)     = o0;
                *(float4*)(g_a + row*D_ + n0 + 4) = o1;
            }
        }
    }
}

// =================================================================
// Kernel 3: sequential scan. grid (B, 4 m-chunks of 16), 128 thr (one d each).
// NO block syncs: w broadcast via direct LDG (L1 broadcast), prefetched 1 step.
// =================================================================
__global__ void __launch_bounds__(128) k_scan(const float* __restrict__ Mv0, float* __restrict__ out) {
    const int b   = blockIdx.x;
    const int mc  = blockIdx.y;
    const int tid = threadIdx.x;   // d
    const int m0  = mc * 16;
    float Mv[16];

    float* mvout = out + BT_ + (size_t)b * TP1_ * M_ * D_;
#pragma unroll
    for (int i = 0; i < 16; i++) {
        float v = Mv0[(m0 + i) * D_ + tid];
        Mv[i] = v;
        __stcs(mvout + (size_t)(m0 + i) * D_ + tid, v);   // t = 0 slice
    }

    const float* wb  = g_w + (size_t)b * T_ * M_ + m0;
    const float* ebp = g_e + (size_t)b * T_ * D_ + tid;
    const float* abp = g_a + (size_t)b * T_ * D_ + tid;
    float* rp = ((mc==0)?g_rp0:(mc==1)?g_rp1:(mc==2)?g_rp2:g_rp3) + (size_t)b * T_ * D_ + tid;

    float4 w0 = *(const float4*)(wb);
    float4 w1 = *(const float4*)(wb + 4);
    float4 w2 = *(const float4*)(wb + 8);
    float4 w3 = *(const float4*)(wb + 12);
    float ecur = ebp[0], acur = abp[0];
    float* orow = mvout + (size_t)M_ * D_ + (size_t)m0 * D_ + tid;

    for (int t = 0; t < T_; t++) {
        float4 nw0=w0, nw1=w1, nw2=w2, nw3=w3;
        float enx = ecur, anx = acur;
        if (t + 1 < T_) {
            const float* wn = wb + (size_t)(t+1)*M_;
            nw0 = *(const float4*)(wn);     nw1 = *(const float4*)(wn + 4);
            nw2 = *(const float4*)(wn + 8); nw3 = *(const float4*)(wn + 12);
            enx = ebp[(size_t)(t+1)*D_];
            anx = abp[(size_t)(t+1)*D_];
        }
        float wv[16] = {w0.x,w0.y,w0.z,w0.w, w1.x,w1.y,w1.z,w1.w,
                        w2.x,w2.y,w2.z,w2.w, w3.x,w3.y,w3.z,w3.w};
        float r0=0.f, r1=0.f;
#pragma unroll
        for (int i = 0; i < 16; i++) {
            float wvi = wv[i];
            if (i & 1) r1 = fmaf(wvi, Mv[i], r1); else r0 = fmaf(wvi, Mv[i], r0);
            Mv[i] = fmaf(wvi, acur, Mv[i] * fmaf(-wvi, ecur, 1.0f));    // Mv*(1-w e)+w a
            __stcs(orow + (size_t)i * D_, Mv[i]);
        }
        rp[(size_t)t * D_] = r0 + r1;
        w0=nw0; w1=nw1; w2=nw2; w3=nw3;
        ecur = enx; acur = anx;
        orow += (size_t)M_ * D_;
    }
}

// =================================================================
// Kernel 4: read = sum(rp0..3); f = tanh([read,k]@fW^T + fb);
// p = sigmoid(f . pW + pb). 32 rows x 128 cols per CTA (grid 400!),
// 128 threads, proven 4x8 thread tiles. Software-pipelined.
// =================================================================
__global__ void __launch_bounds__(128) k_fp(const float* __restrict__ fW, const float* __restrict__ fb,
                                            const float* __restrict__ pW, const float* __restrict__ pb,
                                            float* __restrict__ out) {
    __shared__ __align__(16) float sxT[32*36];
    __shared__ __align__(16) float swT[32*132];
    __shared__ float sp[32*17];
    const int tid  = threadIdx.x;
    const int row0 = blockIdx.x * 32;
    const int ti = tid & 7, tn = tid >> 3;   // rows ti*4.. (32), cols tn*8.. (128)

    int rA[2], kA[2], nB[8], kB[8];
#pragma unroll
    for (int it = 0; it < 2; it++) {
        int idx = it*128 + tid;
        rA[it] = idx >> 3; kA[it] = (idx & 7) << 2;   // rows 0..31
    }
#pragma unroll
    for (int it = 0; it < 8; it++) {
        int idx = it*128 + tid;
        nB[it] = idx >> 3; kB[it] = (idx & 7) << 2;   // cols 0..127
    }

    auto loadX = [&](int row, int kk) -> float4 {
        if (kk < 128) {
            size_t g = (size_t)(row0+row)*D_ + kk;
            float4 a0 = *(const float4*)(g_rp0+g);
            float4 a1 = *(const float4*)(g_rp1+g);
            float4 a2 = *(const float4*)(g_rp2+g);
            float4 a3 = *(const float4*)(g_rp3+g);
            float4 v;
            v.x=(a0.x+a1.x)+(a2.x+a3.x); v.y=(a0.y+a1.y)+(a2.y+a3.y);
            v.z=(a0.z+a1.z)+(a2.z+a3.z); v.w=(a0.w+a1.w)+(a2.w+a3.w);
            return v;
        }
        return *(const float4*)(g_k + (size_t)(row0+row)*D_ + (kk-128));
    };

    float4 xr[2], wr[8];
#pragma unroll
    for (int it = 0; it < 2; it++) xr[it] = loadX(rA[it], kA[it]);
#pragma unroll
    for (int it = 0; it < 8; it++) wr[it] = *(const float4*)(fW + (size_t)nB[it]*256 + kB[it]);

    unsigned long long acc[4][4] = {};
    for (int kc = 0; kc < 8; kc++) {
        if (kc) __syncthreads();
#pragma unroll
        for (int it = 0; it < 2; it++) {
            int k4 = kA[it], row = rA[it];
            sxT[(k4+0)*36+row]=xr[it].x; sxT[(k4+1)*36+row]=xr[it].y;
            sxT[(k4+2)*36+row]=xr[it].z; sxT[(k4+3)*36+row]=xr[it].w;
        }
#pragma unroll
        for (int it = 0; it < 8; it++) {
            int k4 = kB[it], n = nB[it];
            swT[(k4+0)*132+n]=wr[it].x; swT[(k4+1)*132+n]=wr[it].y;
            swT[(k4+2)*132+n]=wr[it].z; swT[(k4+3)*132+n]=wr[it].w;
        }
        __syncthreads();
        if (kc < 7) {
            int kk = (kc+1)*32;
#pragma unroll
            for (int it = 0; it < 2; it++) xr[it] = loadX(rA[it], kk + kA[it]);
#pragma unroll
            for (int it = 0; it < 8; it++) wr[it] = *(const float4*)(fW + (size_t)nB[it]*256 + kk + kB[it]);
        }
#pragma unroll 8
        for (int k = 0; k < 32; k++) mm_step<36,132>(acc, sxT, swT, k, ti, tn);
    }

    // epilogue: f = tanh(acc + fb), partial p = sum pW*f
    float ps[4] = {0.f, 0.f, 0.f, 0.f};
#pragma unroll
    for (int c = 0; c < 4; c++) {
        int n = tn*8 + 2*c;
        float blo = fb[n], bhi = fb[n+1];
        float wlo = pW[n], whi = pW[n+1];
#pragma unroll
        for (int i = 0; i < 4; i++) {
            float lo, hi; unpack2(acc[i][c], lo, hi);
            ps[i] = fmaf(wlo, tanhf(lo + blo), ps[i]);
            ps[i] = fmaf(whi, tanhf(hi + bhi), ps[i]);
        }
    }
#pragma unroll
    for (int i = 0; i < 4; i++) sp[(ti*4+i)*17 + tn] = ps[i];
    __syncthreads();
    if (tid < 32) {
        float s = pb[0];
#pragma unroll
        for (int g2 = 0; g2 < 16; g2++) s += sp[tid*17 + g2];
        out[row0 + tid] = 1.0f / (1.0f + expf(-s));
    }
}

// =================================================================
extern "C" void kernel_launch(void* const* d_in, const int* in_sizes, int n_in,
                              void* d_out, int out_size) {
    const int*   q     = (const int*)  d_in[0];
    const int*   r     = (const int*)  d_in[1];
    const float* k_emb = (const float*)d_in[2];
    const float* v_emb = (const float*)d_in[3];
    const float* Mk    = (const float*)d_in[4];
    const float* Mv0   = (const float*)d_in[5];
    const float* fW    = (const float*)d_in[6];
    const float* fb    = (const float*)d_in[7];
    const float* pW    = (const float*)d_in[8];
    const float* pb    = (const float*)d_in[9];
    const float* eW    = (const float*)d_in[10];
    const float* eb    = (const float*)d_in[11];
    const float* aW    = (const float*)d_in[12];
    const float* ab    = (const float*)d_in[13];
    float* out = (float*)d_out;

    k_we   <<<dim3(BT_/64, 5), 128>>>(q, r, k_emb, Mk, v_emb, eW, eb, aW, ab);
    k_scan <<<dim3(B_, 4), 128>>>(Mv0, out);
    k_fp   <<<BT_/32, 128>>>(fW, fb, pW, pb, out);
}